// round 15
// baseline (speedup 1.0000x reference)
#include <cuda_runtime.h>
#include <cuda_bf16.h>
#include <math.h>

// ---------------- problem constants ----------------
#define BATCH 2
#define CCH   512
#define NPIX  1024     // 32*32
#define GR    8
#define CG    64
#define NBG   16       // BATCH*GR
#define KVP   64       // 8*8
#define DIMH  64
#define SCALE 0.125f
#define EPSBN 1e-5f

// ---------------- bf16x2 / tf32 / mma helpers ----------------
__device__ __forceinline__ unsigned pack_bf16(float lo, float hi) {
    unsigned r;
    asm("cvt.rn.bf16x2.f32 %0, %1, %2;" : "=r"(r) : "f"(hi), "f"(lo));
    return r;
}
__device__ __forceinline__ unsigned to_tf32(float v) {
    unsigned r;
    asm("cvt.rna.tf32.f32 %0, %1;" : "=r"(r) : "f"(v));
    return r;
}
__device__ __forceinline__ void mma_bf16(float& c0, float& c1, float& c2, float& c3,
                                         unsigned a0, unsigned a1, unsigned a2, unsigned a3,
                                         unsigned b0, unsigned b1) {
    asm volatile("mma.sync.aligned.m16n8k16.row.col.f32.bf16.bf16.f32 "
        "{%0,%1,%2,%3}, {%4,%5,%6,%7}, {%8,%9}, {%0,%1,%2,%3};"
        : "+f"(c0), "+f"(c1), "+f"(c2), "+f"(c3)
        : "r"(a0), "r"(a1), "r"(a2), "r"(a3), "r"(b0), "r"(b1));
}
__device__ __forceinline__ void mma_tf32(float& c0, float& c1, float& c2, float& c3,
                                         unsigned a0, unsigned a1, unsigned a2, unsigned a3,
                                         unsigned b0, unsigned b1) {
    asm volatile("mma.sync.aligned.m16n8k8.row.col.f32.tf32.tf32.f32 "
        "{%0,%1,%2,%3}, {%4,%5,%6,%7}, {%8,%9}, {%0,%1,%2,%3};"
        : "+f"(c0), "+f"(c1), "+f"(c2), "+f"(c3)
        : "r"(a0), "r"(a1), "r"(a2), "r"(a3), "r"(b0), "r"(b1));
}

// ---------------- device scratch (no allocation allowed) ----------------
__device__ float g_s1[CCH], g_t1[CCH], g_s2[CCH], g_t2[CCH];
__device__ float g_q [BATCH*CCH*NPIX];      // grouped conv q (unscaled)
__device__ float g_offpart[NBG*16*KVP*2];   // offset partials
__device__ float g_vgrid[NBG*KVP*2];        // normalized sample grid (vx,vy)
__device__ float g_kv[NBG*CG*KVP];          // sampled features
__device__ float g_k [NBG*CG*KVP];
__device__ float g_v [NBG*CG*KVP];
__device__ float g_bias[NBG*NPIX*KVP];      // CPB bias
__device__ float g_attn[BATCH*CCH*NPIX];    // attention output
__device__ float g_x2[BATCH*CCH*NPIX];      // x + out-proj
__device__ float g_h [BATCH*4*CCH*NPIX];    // FFN hidden

// ---------------- batchnorm stats ----------------
__global__ void bn_stats(const float* __restrict__ x, const float* __restrict__ g,
                         const float* __restrict__ b, float* __restrict__ s, float* __restrict__ t) {
    int c = blockIdx.x;
    float sum = 0.f, sq = 0.f;
    for (int e = threadIdx.x; e < BATCH*NPIX; e += 256) {
        int bb = e >> 10, p = e & 1023;
        float v = x[(bb*CCH + c)*NPIX + p];
        sum += v; sq += v*v;
    }
    __shared__ float rs[256], rq[256];
    rs[threadIdx.x] = sum; rq[threadIdx.x] = sq;
    __syncthreads();
    for (int st = 128; st > 0; st >>= 1) {
        if (threadIdx.x < st) { rs[threadIdx.x] += rs[threadIdx.x+st]; rq[threadIdx.x] += rq[threadIdx.x+st]; }
        __syncthreads();
    }
    if (threadIdx.x == 0) {
        float m   = rs[0] / (float)(BATCH*NPIX);
        float var = rq[0] / (float)(BATCH*NPIX) - m*m;
        float sc  = g[c] * rsqrtf(var + EPSBN);
        s[c] = sc;
        t[c] = b[c] - m*sc;
    }
}

// ---------------- grouped 1x1 conv with optional bn fold on the input ----------------
__global__ void gconv(const float* __restrict__ in, const float* __restrict__ w,
                      const float* __restrict__ sc, const float* __restrict__ sh,
                      float* __restrict__ out, int npix) {
    int bg = blockIdx.x;
    int g  = bg & (GR-1);
    int pix = blockIdx.y*blockDim.x + threadIdx.x;
    __shared__ float ws[CG*CG];
    for (int e = threadIdx.x; e < CG*CG; e += blockDim.x) ws[e] = w[g*CG*CG + e];
    __syncthreads();
    if (pix >= npix) return;
    float xr[CG];
    #pragma unroll
    for (int ci = 0; ci < CG; ci++) {
        float v = in[(bg*CG + ci)*npix + pix];
        if (sc) v = v*sc[g*CG + ci] + sh[g*CG + ci];
        xr[ci] = v;
    }
    #pragma unroll 4
    for (int o = 0; o < CG; o++) {
        float acc = 0.f;
        #pragma unroll
        for (int ci = 0; ci < CG; ci++) acc += ws[o*CG + ci] * xr[ci];
        out[(bg*CG + o)*npix + pix] = acc;
    }
}

// ---------------- fused k+v grouped conv on sampled features ----------------
__global__ void gconv_kv(const float* __restrict__ kv, const float* __restrict__ kw,
                         const float* __restrict__ vw,
                         float* __restrict__ kout, float* __restrict__ vout) {
    int bg = blockIdx.x;
    int g  = bg & (GR-1);
    int pix = threadIdx.x;   // 64
    __shared__ float wsk[CG*CG], wsv[CG*CG];
    for (int e = threadIdx.x; e < CG*CG; e += 64) {
        wsk[e] = kw[g*CG*CG + e];
        wsv[e] = vw[g*CG*CG + e];
    }
    __syncthreads();
    float xr[CG];
    #pragma unroll
    for (int ci = 0; ci < CG; ci++) xr[ci] = kv[(bg*CG + ci)*KVP + pix];
    #pragma unroll 4
    for (int o = 0; o < CG; o++) {
        float ak = 0.f, av = 0.f;
        #pragma unroll
        for (int ci = 0; ci < CG; ci++) {
            ak += wsk[o*CG + ci] * xr[ci];
            av += wsv[o*CG + ci] * xr[ci];
        }
        kout[(bg*CG + o)*KVP + pix] = ak;
        vout[(bg*CG + o)*KVP + pix] = av;
    }
}

// ---------------- offsets, stage 1: per-channel-group partial sums ----------------
__global__ void offsets_part(const float* __restrict__ q, const float* __restrict__ dww,
                             const float* __restrict__ dwb, const float* __restrict__ pww,
                             float* __restrict__ part) {
    int bg = blockIdx.x, grp = blockIdx.y;
    int tid = threadIdx.x;               // 64 threads, one per 8x8 output pos
    int oy = tid >> 3, ox = tid & 7;
    float acc0 = 0.f, acc1 = 0.f;
    #pragma unroll
    for (int cc = 0; cc < 4; cc++) {
        int c = grp*4 + cc;
        const float* wc = dww + c*36;
        const float* qc = q + (bg*CG + c)*NPIX;
        float s = 0.f;
        #pragma unroll
        for (int ky = 0; ky < 6; ky++) {
            int iy = oy*4 - 1 + ky;
            if (iy < 0 || iy >= 32) continue;
            #pragma unroll
            for (int kx = 0; kx < 6; kx++) {
                int ix = ox*4 - 1 + kx;
                if (ix < 0 || ix >= 32) continue;
                s += wc[ky*6 + kx] * qc[iy*32 + ix];
            }
        }
        s += dwb[c];
        float ge = 0.5f*s*(1.f + erff(s*0.70710678118654752f));  // exact gelu
        acc0 += pww[c]      * ge;
        acc1 += pww[CG + c] * ge;
    }
    part[((bg*16 + grp)*KVP + tid)*2 + 0] = acc0;
    part[((bg*16 + grp)*KVP + tid)*2 + 1] = acc1;
}

// ---------------- fused: offsets finish + bilinear sample of bn1(x) with zero pad ----------------
// v = s[c]*Σ(w·x_valid) + t[c]*Σ(w_valid)
__global__ void gridsample_kernel(const float* __restrict__ x, const float* __restrict__ part,
                                  const float* __restrict__ s1, const float* __restrict__ t1,
                                  float* __restrict__ vgrid, float* __restrict__ kv) {
    __shared__ float vgs[KVP*2];
    int bg = blockIdx.x;
    int g  = bg & (GR-1);
    int tid = threadIdx.x;   // 256
    if (tid < 64) {
        int oy = tid >> 3, ox = tid & 7;
        float a0 = 0.f, a1 = 0.f;
        #pragma unroll
        for (int gg = 0; gg < 16; gg++) {
            a0 += part[((bg*16 + gg)*KVP + tid)*2 + 0];
            a1 += part[((bg*16 + gg)*KVP + tid)*2 + 1];
        }
        float offx = tanhf(a0)*4.f;
        float offy = tanhf(a1)*4.f;
        float vx = 2.f*((float)ox + offx)/7.f - 1.f;
        float vy = 2.f*((float)oy + offy)/7.f - 1.f;
        vgs[tid*2 + 0] = vx;
        vgs[tid*2 + 1] = vy;
        vgrid[bg*(KVP*2) + tid*2 + 0] = vx;
        vgrid[bg*(KVP*2) + tid*2 + 1] = vy;
    }
    __syncthreads();
    for (int e = tid; e < CG*KVP; e += 256) {
        int c = e >> 6, pos = e & 63;
        float vx = vgs[pos*2 + 0];
        float vy = vgs[pos*2 + 1];
        float xf = ((vx + 1.f)*32.f - 1.f)*0.5f;
        float yf = ((vy + 1.f)*32.f - 1.f)*0.5f;
        float x0 = floorf(xf), y0 = floorf(yf);
        float wx = xf - x0, wy = yf - y0;
        int x0i = (int)x0, y0i = (int)y0;
        const float* img = x + (bg*CG + c)*NPIX;
        float w00 = (1.f-wx)*(1.f-wy), w10 = wx*(1.f-wy);
        float w01 = (1.f-wx)*wy,       w11 = wx*wy;
        bool xa = (x0i   >= 0 && x0i   < 32), xb = (x0i+1 >= 0 && x0i+1 < 32);
        bool ya = (y0i   >= 0 && y0i   < 32), yb = (y0i+1 >= 0 && y0i+1 < 32);
        float acc = 0.f, wsum = 0.f;
        if (xa && ya) { acc += w00*img[y0i*32 + x0i];       wsum += w00; }
        if (xb && ya) { acc += w10*img[y0i*32 + x0i+1];     wsum += w10; }
        if (xa && yb) { acc += w01*img[(y0i+1)*32 + x0i];   wsum += w01; }
        if (xb && yb) { acc += w11*img[(y0i+1)*32 + x0i+1]; wsum += w11; }
        int cg = g*CG + c;
        kv[(bg*CG + c)*KVP + pos] = s1[cg]*acc + t1[cg]*wsum;
    }
}

// ---------------- CPB bias MLP with bf16 tensor cores ----------------
// 2048 blocks x 256 threads, 2 CTAs/SM. Block owns (bg, 8 i values) = 512 points, 4 passes of 128.
#define BIAS_SMEM_BYTES ((128*68*2 + 256 + 128 + 128 + 128)*4)
__global__ void __launch_bounds__(256, 2)
bias_kernel(const float* __restrict__ vgrid,
            const float* __restrict__ w0, const float* __restrict__ b0,
            const float* __restrict__ w1, const float* __restrict__ b1,
            const float* __restrict__ w2, const float* __restrict__ b2,
            float* __restrict__ bias_out) {
    extern __shared__ unsigned smu[];
    unsigned* w1tb = smu;                 // [col][kp] stride 68
    unsigned* h1b  = smu + 128*68;        // [p][kp]   stride 68
    float* fsm = (float*)(smu + 2*128*68);
    float* w0s = fsm;                     // 256
    float* b0s = fsm + 256;               // 128
    float* b1s = fsm + 384;               // 128
    float* w2s = fsm + 512;               // 128

    int tid = threadIdx.x;
    int bg  = blockIdx.x >> 7;
    int i0  = (blockIdx.x & 127) << 3;
    int w   = tid >> 5, lane = tid & 31;
    int g   = lane >> 2, t4 = lane & 3;

    for (int e = tid; e < 128*64; e += 256) {
        int col = e & 127, kp = e >> 7;
        float lo = w1[(2*kp)*128 + col];
        float hi = w1[(2*kp+1)*128 + col];
        w1tb[col*68 + kp] = pack_bf16(lo, hi);
    }
    w0s[tid] = w0[tid];
    if (tid < 128) { b0s[tid] = b0[tid]; b1s[tid] = b1[tid]; w2s[tid] = w2[tid]; }
    float b2v = b2[0];

    int p_h = tid >> 1;
    int half = (tid & 1) * 32;
    int j_h = p_h & 63;
    float vx_t = vgrid[bg*(KVP*2) + j_h*2 + 0];
    float vy_t = vgrid[bg*(KVP*2) + j_h*2 + 1];

    __syncthreads();

    for (int pass = 0; pass < 4; pass++) {
        if (pass) __syncthreads();
        {
            int i = i0 + pass*2 + (p_h >> 6);
            float qx = 2.f*(float)(i & 31)/31.f - 1.f;
            float qy = 2.f*(float)(i >> 5)/31.f - 1.f;
            float px = qx - vx_t;
            float py = qy - vy_t;
            float f0 = copysignf(log1pf(fabsf(px)), px);
            float f1 = copysignf(log1pf(fabsf(py)), py);
            #pragma unroll 8
            for (int kp = half; kp < half + 32; kp++) {
                int k0i = 2*kp;
                float hlo = f0*w0s[k0i]   + f1*w0s[128 + k0i]   + b0s[k0i];
                float hhi = f0*w0s[k0i+1] + f1*w0s[128 + k0i+1] + b0s[k0i+1];
                hlo = hlo > 0.f ? hlo : 0.f;
                hhi = hhi > 0.f ? hhi : 0.f;
                h1b[p_h*68 + kp] = pack_bf16(hlo, hhi);
            }
        }
        __syncthreads();

        float acc[16][4];
        #pragma unroll
        for (int nt = 0; nt < 16; nt++)
            #pragma unroll
            for (int c = 0; c < 4; c++) acc[nt][c] = 0.f;

        #pragma unroll
        for (int ks = 0; ks < 8; ks++) {
            int abase = (w*16 + g)*68 + ks*8 + t4;
            unsigned a0 = h1b[abase];
            unsigned a1 = h1b[abase + 8*68];
            unsigned a2 = h1b[abase + 4];
            unsigned a3 = h1b[abase + 8*68 + 4];
            #pragma unroll
            for (int nt = 0; nt < 16; nt++) {
                int bbase = (nt*8 + g)*68 + ks*8 + t4;
                unsigned bb0 = w1tb[bbase];
                unsigned bb1 = w1tb[bbase + 4];
                mma_bf16(acc[nt][0], acc[nt][1], acc[nt][2], acc[nt][3],
                         a0, a1, a2, a3, bb0, bb1);
            }
        }

        float plo = 0.f, phi = 0.f;
        #pragma unroll
        for (int nt = 0; nt < 16; nt++) {
            int col = nt*8 + 2*t4;
            float bl0 = b1s[col], bl1 = b1s[col+1];
            float wl0 = w2s[col], wl1 = w2s[col+1];
            float h;
            h = acc[nt][0] + bl0; plo += (h > 0.f ? h : 0.f)*wl0;
            h = acc[nt][1] + bl1; plo += (h > 0.f ? h : 0.f)*wl1;
            h = acc[nt][2] + bl0; phi += (h > 0.f ? h : 0.f)*wl0;
            h = acc[nt][3] + bl1; phi += (h > 0.f ? h : 0.f)*wl1;
        }
        plo += __shfl_xor_sync(0xffffffffu, plo, 1);
        plo += __shfl_xor_sync(0xffffffffu, plo, 2);
        phi += __shfl_xor_sync(0xffffffffu, phi, 1);
        phi += __shfl_xor_sync(0xffffffffu, phi, 2);
        if (t4 == 0) {
            int plo_p = w*16 + g;
            int phi_p = plo_p + 8;
            int ilo = i0 + pass*2 + (plo_p >> 6);
            int ihi = i0 + pass*2 + (phi_p >> 6);
            bias_out[((bg << 10) + ilo)*KVP + (plo_p & 63)] = plo + b2v;
            bias_out[((bg << 10) + ihi)*KVP + (phi_p & 63)] = phi + b2v;
        }
    }
}

// ---------------- attention: sim + bias, softmax over 64 kv, @V ----------------
#define ATT_QT 128
#define ATT_SMEM_FLOATS (64*64 + 64*64 + ATT_QT*65)
__global__ void attn_kernel(const float* __restrict__ q, const float* __restrict__ karr,
                            const float* __restrict__ varr, const float* __restrict__ bias,
                            float* __restrict__ outp) {
    extern __shared__ float sm[];
    float* ks = sm;                 // [j][d]
    float* vs = sm + 64*64;         // [j][d]
    float* ss = sm + 2*64*64;       // [tid][65]
    int bg = blockIdx.x;
    int i  = blockIdx.y*ATT_QT + threadIdx.x;
    for (int e = threadIdx.x; e < CG*KVP; e += ATT_QT) {
        int d = e >> 6, j = e & 63;
        ks[j*64 + d] = karr[(bg*CG + d)*KVP + j];
        vs[j*64 + d] = varr[(bg*CG + d)*KVP + j];
    }
    __syncthreads();
    float qr[DIMH];
    #pragma unroll
    for (int d = 0; d < DIMH; d++) qr[d] = q[(bg*CG + d)*NPIX + i] * SCALE;
    const float* brow = bias + (bg*NPIX + i)*KVP;
    float m = -1e30f;
    for (int j = 0; j < KVP; j++) {
        float s = 0.f;
        #pragma unroll
        for (int d = 0; d < DIMH; d++) s += qr[d]*ks[j*64 + d];
        s += brow[j];
        ss[threadIdx.x*65 + j] = s;
        m = fmaxf(m, s);
    }
    float l = 0.f;
    float o[DIMH];
    #pragma unroll
    for (int d = 0; d < DIMH; d++) o[d] = 0.f;
    for (int j = 0; j < KVP; j++) {
        float p = expf(ss[threadIdx.x*65 + j] - m);
        l += p;
        #pragma unroll
        for (int d = 0; d < DIMH; d++) o[d] += p*vs[j*64 + d];
    }
    float inv = 1.f / l;
    #pragma unroll
    for (int d = 0; d < DIMH; d++) outp[(bg*CG + d)*NPIX + i] = o[d]*inv;
}

// ---------------- bf16 tensor-core SGEMM (out-proj only) ----------------
__global__ void __launch_bounds__(256, 1)
sgemm_tc(const float* __restrict__ A, const float* __restrict__ B,
         const float* __restrict__ bias, const float* __restrict__ scaleB,
         const float* __restrict__ shiftB, const float* __restrict__ resid,
         float* __restrict__ C, int M, int N, int K, int act) {
    __shared__ unsigned Ab[128*20];
    __shared__ unsigned Bb[128*20];
    int tid = threadIdx.x;
    int n0 = blockIdx.x*128, m0 = blockIdx.y*128;
    int zB = blockIdx.z * K * N;
    int zC = blockIdx.z * M * N;
    int w = tid >> 5, lane = tid & 31;
    int g = lane >> 2, t4 = lane & 3;
    int wm = w & 1, wn = w >> 1;

    float acc[4][4][4];
    #pragma unroll
    for (int mt = 0; mt < 4; mt++)
        #pragma unroll
        for (int nt = 0; nt < 4; nt++)
            #pragma unroll
            for (int c = 0; c < 4; c++) acc[mt][nt][c] = 0.f;

    for (int k0 = 0; k0 < K; k0 += 32) {
        #pragma unroll
        for (int s = 0; s < 8; s++) {
            int e = tid + s*256;
            int kp = e & 15, row = e >> 4;
            float2 v = *reinterpret_cast<const float2*>(&A[(m0 + row)*K + k0 + 2*kp]);
            Ab[row*20 + kp] = pack_bf16(v.x, v.y);
        }
        #pragma unroll
        for (int s = 0; s < 8; s++) {
            int e = tid + s*256;
            int col = e & 127, kp = e >> 7;
            int kk = k0 + 2*kp;
            float blo = B[zB + kk*N + n0 + col];
            float bhi = B[zB + (kk+1)*N + n0 + col];
            if (scaleB) {
                blo = blo*scaleB[kk]   + shiftB[kk];
                bhi = bhi*scaleB[kk+1] + shiftB[kk+1];
            }
            Bb[col*20 + kp] = pack_bf16(blo, bhi);
        }
        __syncthreads();

        #pragma unroll
        for (int kseg = 0; kseg < 2; kseg++) {
            unsigned afr[4][4], bfr[4][2];
            #pragma unroll
            for (int mt = 0; mt < 4; mt++) {
                int ab = (wm*64 + mt*16 + g)*20 + kseg*8 + t4;
                afr[mt][0] = Ab[ab];
                afr[mt][1] = Ab[ab + 8*20];
                afr[mt][2] = Ab[ab + 4];
                afr[mt][3] = Ab[ab + 8*20 + 4];
            }
            #pragma unroll
            for (int nt = 0; nt < 4; nt++) {
                int bb = (wn*32 + nt*8 + g)*20 + kseg*8 + t4;
                bfr[nt][0] = Bb[bb];
                bfr[nt][1] = Bb[bb + 4];
            }
            #pragma unroll
            for (int mt = 0; mt < 4; mt++)
                #pragma unroll
                for (int nt = 0; nt < 4; nt++)
                    mma_bf16(acc[mt][nt][0], acc[mt][nt][1], acc[mt][nt][2], acc[mt][nt][3],
                             afr[mt][0], afr[mt][1], afr[mt][2], afr[mt][3],
                             bfr[nt][0], bfr[nt][1]);
        }
        __syncthreads();
    }

    #pragma unroll
    for (int mt = 0; mt < 4; mt++) {
        #pragma unroll
        for (int hf = 0; hf < 2; hf++) {
            int m = m0 + wm*64 + mt*16 + g + hf*8;
            float bm = bias[m];
            #pragma unroll
            for (int nt = 0; nt < 4; nt++) {
                int col = n0 + wn*32 + nt*8 + 2*t4;
                float v0 = acc[mt][nt][hf*2]     + bm;
                float v1 = acc[mt][nt][hf*2 + 1] + bm;
                if (act == 1) {
                    v0 = 0.5f*v0*(1.f + erff(v0*0.70710678118654752f));
                    v1 = 0.5f*v1*(1.f + erff(v1*0.70710678118654752f));
                }
                if (resid) {
                    float2 rv = *reinterpret_cast<const float2*>(&resid[zC + m*N + col]);
                    v0 += rv.x; v1 += rv.y;
                }
                float2 ov; ov.x = v0; ov.y = v1;
                *reinterpret_cast<float2*>(&C[zC + m*N + col]) = ov;
            }
        }
    }
}

// ---------------- tf32 tensor-core SGEMM (FFN, higher precision) ----------------
// Same 128x128 block / 8 warps; k-chunk 16, two m16n8k8 segments.
__global__ void __launch_bounds__(256, 1)
sgemm_tf32(const float* __restrict__ A, const float* __restrict__ B,
           const float* __restrict__ bias, const float* __restrict__ scaleB,
           const float* __restrict__ shiftB, const float* __restrict__ resid,
           float* __restrict__ C, int M, int N, int K, int act) {
    __shared__ unsigned Ab[128*20];   // [row][k] stride 20 (16 data + 4 pad), tf32 bits
    __shared__ unsigned Bb[128*20];   // [col][k] stride 20
    int tid = threadIdx.x;
    int n0 = blockIdx.x*128, m0 = blockIdx.y*128;
    int zB = blockIdx.z * K * N;
    int zC = blockIdx.z * M * N;
    int w = tid >> 5, lane = tid & 31;
    int g = lane >> 2, t4 = lane & 3;
    int wm = w & 1, wn = w >> 1;

    float acc[4][4][4];
    #pragma unroll
    for (int mt = 0; mt < 4; mt++)
        #pragma unroll
        for (int nt = 0; nt < 4; nt++)
            #pragma unroll
            for (int c = 0; c < 4; c++) acc[mt][nt][c] = 0.f;

    for (int k0 = 0; k0 < K; k0 += 16) {
        // A tile: 128 rows x 16 k
        #pragma unroll
        for (int s = 0; s < 8; s++) {
            int e = tid + s*256;
            int kk = e & 15, row = e >> 4;
            Ab[row*20 + kk] = to_tf32(A[(m0 + row)*K + k0 + kk]);
        }
        // B tile: 16 k x 128 cols, optional bn fold
        #pragma unroll
        for (int s = 0; s < 8; s++) {
            int e = tid + s*256;
            int col = e & 127, kk = e >> 7;
            float bv = B[zB + (k0 + kk)*N + n0 + col];
            if (scaleB) bv = bv*scaleB[k0 + kk] + shiftB[k0 + kk];
            Bb[col*20 + kk] = to_tf32(bv);
        }
        __syncthreads();

        #pragma unroll
        for (int kseg = 0; kseg < 2; kseg++) {
            unsigned afr[4][4], bfr[4][2];
            #pragma unroll
            for (int mt = 0; mt < 4; mt++) {
                int ab = (wm*64 + mt*16 + g)*20 + kseg*8 + t4;
                afr[mt][0] = Ab[ab];
                afr[mt][1] = Ab[ab + 8*20];
                afr[mt][2] = Ab[ab + 4];
                afr[mt][3] = Ab[ab + 8*20 + 4];
            }
            #pragma unroll
            for (int nt = 0; nt < 4; nt++) {
                int bb = (wn*32 + nt*8 + g)*20 + kseg*8 + t4;
                bfr[nt][0] = Bb[bb];
                bfr[nt][1] = Bb[bb + 4];
            }
            #pragma unroll
            for (int mt = 0; mt < 4; mt++)
                #pragma unroll
                for (int nt = 0; nt < 4; nt++)
                    mma_tf32(acc[mt][nt][0], acc[mt][nt][1], acc[mt][nt][2], acc[mt][nt][3],
                             afr[mt][0], afr[mt][1], afr[mt][2], afr[mt][3],
                             bfr[nt][0], bfr[nt][1]);
        }
        __syncthreads();
    }

    #pragma unroll
    for (int mt = 0; mt < 4; mt++) {
        #pragma unroll
        for (int hf = 0; hf < 2; hf++) {
            int m = m0 + wm*64 + mt*16 + g + hf*8;
            float bm = bias[m];
            #pragma unroll
            for (int nt = 0; nt < 4; nt++) {
                int col = n0 + wn*32 + nt*8 + 2*t4;
                float v0 = acc[mt][nt][hf*2]     + bm;
                float v1 = acc[mt][nt][hf*2 + 1] + bm;
                if (act == 1) {
                    v0 = 0.5f*v0*(1.f + erff(v0*0.70710678118654752f));
                    v1 = 0.5f*v1*(1.f + erff(v1*0.70710678118654752f));
                }
                if (resid) {
                    float2 rv = *reinterpret_cast<const float2*>(&resid[zC + m*N + col]);
                    v0 += rv.x; v1 += rv.y;
                }
                float2 ov; ov.x = v0; ov.y = v1;
                *reinterpret_cast<float2*>(&C[zC + m*N + col]) = ov;
            }
        }
    }
}

// ---------------- launch ----------------
extern "C" void kernel_launch(void* const* d_in, const int* in_sizes, int n_in,
                              void* d_out, int out_size) {
    const float* x        = (const float*)d_in[0];
    const float* n1_g     = (const float*)d_in[1];
    const float* n1_b     = (const float*)d_in[2];
    const float* n2_g     = (const float*)d_in[3];
    const float* n2_b     = (const float*)d_in[4];
    const float* q_w      = (const float*)d_in[5];
    const float* k_w      = (const float*)d_in[6];
    const float* v_w      = (const float*)d_in[7];
    const float* off_dw_w = (const float*)d_in[8];
    const float* off_dw_b = (const float*)d_in[9];
    const float* off_pw_w = (const float*)d_in[10];
    const float* cpb_w0   = (const float*)d_in[11];
    const float* cpb_b0   = (const float*)d_in[12];
    const float* cpb_w1   = (const float*)d_in[13];
    const float* cpb_b1   = (const float*)d_in[14];
    const float* cpb_w2   = (const float*)d_in[15];
    const float* cpb_b2   = (const float*)d_in[16];
    const float* out_w    = (const float*)d_in[17];
    const float* out_b    = (const float*)d_in[18];
    const float* mlp_w1   = (const float*)d_in[19];
    const float* mlp_b1   = (const float*)d_in[20];
    const float* mlp_w2   = (const float*)d_in[21];
    const float* mlp_b2   = (const float*)d_in[22];
    float* out = (float*)d_out;

    float *p_s1, *p_t1, *p_s2, *p_t2, *p_q, *p_op, *p_vg, *p_kv, *p_k, *p_v, *p_bias, *p_attn, *p_x2, *p_h;
    cudaGetSymbolAddress((void**)&p_s1, g_s1);
    cudaGetSymbolAddress((void**)&p_t1, g_t1);
    cudaGetSymbolAddress((void**)&p_s2, g_s2);
    cudaGetSymbolAddress((void**)&p_t2, g_t2);
    cudaGetSymbolAddress((void**)&p_q,  g_q);
    cudaGetSymbolAddress((void**)&p_op, g_offpart);
    cudaGetSymbolAddress((void**)&p_vg, g_vgrid);
    cudaGetSymbolAddress((void**)&p_kv, g_kv);
    cudaGetSymbolAddress((void**)&p_k,  g_k);
    cudaGetSymbolAddress((void**)&p_v,  g_v);
    cudaGetSymbolAddress((void**)&p_bias, g_bias);
    cudaGetSymbolAddress((void**)&p_attn, g_attn);
    cudaGetSymbolAddress((void**)&p_x2, g_x2);
    cudaGetSymbolAddress((void**)&p_h,  g_h);

    cudaFuncSetAttribute(bias_kernel, cudaFuncAttributeMaxDynamicSharedMemorySize,
                         BIAS_SMEM_BYTES);
    cudaFuncSetAttribute(attn_kernel, cudaFuncAttributeMaxDynamicSharedMemorySize,
                         ATT_SMEM_FLOATS*4);

    // 1) bn1 stats
    bn_stats<<<CCH, 256>>>(x, n1_g, n1_b, p_s1, p_t1);
    // 2) q = grouped conv on bn1(x) (bn folded into load)
    gconv<<<dim3(NBG, 4), 256>>>(x, q_w, p_s1, p_t1, p_q, NPIX);
    // 3) offsets partials
    offsets_part<<<dim3(NBG, 16), 64>>>(p_q, off_dw_w, off_dw_b, off_pw_w, p_op);
    // 4) fused offsets-finish + bilinear sample of bn1(x)
    gridsample_kernel<<<NBG, 256>>>(x, p_op, p_s1, p_t1, p_vg, p_kv);
    // 5) fused k+v grouped convs
    gconv_kv<<<NBG, 64>>>(p_kv, k_w, v_w, p_k, p_v);
    // 6) CPB bias MLP (bf16 tensor cores)
    bias_kernel<<<NBG*128, 256, BIAS_SMEM_BYTES>>>(p_vg, cpb_w0, cpb_b0, cpb_w1, cpb_b1,
                                                   cpb_w2, cpb_b2, p_bias);
    // 7) attention
    attn_kernel<<<dim3(NBG, NPIX/ATT_QT), ATT_QT, ATT_SMEM_FLOATS*4>>>(p_q, p_k, p_v, p_bias, p_attn);
    // 8) out projection + residual (bf16 — error contribution negligible)
    sgemm_tc<<<dim3(8, 4, BATCH), 256>>>(out_w, p_attn, out_b, nullptr, nullptr, x, p_x2,
                                         512, 1024, 512, 0);
    // 9) bn2 + FFN (tf32 — accuracy-critical path)
    bn_stats<<<CCH, 256>>>(p_x2, n2_g, n2_b, p_s2, p_t2);
    sgemm_tf32<<<dim3(8, 16, BATCH), 256>>>(mlp_w1, p_x2, mlp_b1, p_s2, p_t2, nullptr, p_h,
                                            2048, 1024, 512, 1);
    sgemm_tf32<<<dim3(8, 4, BATCH), 256>>>(mlp_w2, p_h, mlp_b2, nullptr, nullptr, p_x2, out,
                                           512, 1024, 2048, 0);
}